// round 3
// baseline (speedup 1.0000x reference)
#include <cuda_runtime.h>
#include <cuda_bf16.h>
#include <math.h>

// Problem constants
#define Lc 15
#define Dc 512
#define Hc 64
#define HDc 8
#define Fc 2048
#define Gc 128
#define Bc 4
#define Nc 256
#define Mc (Bc*Nc)   // 1024 rows
#define SPLITK 4

// -------- scratch (device globals; no allocation allowed) --------
__device__ float g_h[Mc*Dc];
__device__ float g_x[Mc*Dc];
__device__ float g_qkv[Mc*3*Dc];
__device__ float g_attn[Mc*Dc];
__device__ float g_ffn[Mc*Fc];
__device__ float g_pair[Bc*Nc*Nc];
__device__ float g_split[SPLITK*Mc*Dc];

// ---------------- embedding ----------------
__global__ void emb_kernel(const int* __restrict__ atom_types,
                           const float* __restrict__ atom_emb,
                           float* __restrict__ h) {
    int idx = blockIdx.x * blockDim.x + threadIdx.x;   // Mc*Dc threads
    if (idx >= Mc*Dc) return;
    int row = idx >> 9;          // /512
    int d   = idx & 511;
    h[idx] = atom_emb[atom_types[row]*Dc + d];
}

// ---------------- pair representation ----------------
__global__ void pair_kernel(const float* __restrict__ coords,
                            const int* __restrict__ ptypes,
                            const float* __restrict__ pa,
                            const float* __restrict__ pb,
                            const float* __restrict__ mu,
                            const float* __restrict__ sigma,
                            const float* __restrict__ plw,
                            const float* __restrict__ plb,
                            float* __restrict__ pr) {
    __shared__ float smu[Gc], scoef[Gc];
    int tid = threadIdx.x;
    if (tid < Gc) {
        float sg = sigma[tid];
        scoef[tid] = plw[tid] / (2.0f*sg*sg) / (sg * 2.5066282746310002f);
        smu[tid]   = mu[tid];
    }
    __syncthreads();
    int p = blockIdx.x * blockDim.x + tid;             // B*N*N entries
    int b = p >> 16;
    int rem = p & 65535;
    int i = rem >> 8, j = rem & 255;
    const float* ci = coords + (b*Nc + i)*3;
    const float* cj = coords + (b*Nc + j)*3;
    float dx = ci[0]-cj[0], dy = ci[1]-cj[1], dz = ci[2]-cj[2];
    float d2 = dx*dx + dy*dy + dz*dz;
    float dist = sqrtf(fmaxf(d2, 1e-12f));
    int pt = ptypes[p];
    float da = pa[pt]*dist + pb[pt];
    float s = 0.f;
    #pragma unroll 8
    for (int g = 0; g < Gc; g++) {
        float t = da - smu[g];
        s += __expf(-t*t) * scoef[g];
    }
    pr[p] = s + plb[0];
}

// ---------------- layernorm ----------------
__global__ __launch_bounds__(128) void ln_kernel(const float* __restrict__ in,
                                                 const float* __restrict__ g,
                                                 const float* __restrict__ bb,
                                                 float* __restrict__ out) {
    int row = blockIdx.x;
    int tid = threadIdx.x;
    const float* x = in + row*Dc;
    float v[4], s = 0.f, s2 = 0.f;
    #pragma unroll
    for (int j = 0; j < 4; j++) {
        v[j] = x[tid + 128*j];
        s += v[j]; s2 += v[j]*v[j];
    }
    #pragma unroll
    for (int off = 16; off; off >>= 1) {
        s  += __shfl_xor_sync(0xffffffff, s,  off);
        s2 += __shfl_xor_sync(0xffffffff, s2, off);
    }
    __shared__ float rs[4], rs2[4];
    int wid = tid >> 5, lane = tid & 31;
    if (lane == 0) { rs[wid] = s; rs2[wid] = s2; }
    __syncthreads();
    s  = rs[0]+rs[1]+rs[2]+rs[3];
    s2 = rs2[0]+rs2[1]+rs2[2]+rs2[3];
    float mean = s * (1.0f/Dc);
    float var  = s2 * (1.0f/Dc) - mean*mean;
    float rstd = rsqrtf(var + 1e-5f);
    #pragma unroll
    for (int j = 0; j < 4; j++) {
        int d = tid + 128*j;
        out[row*Dc + d] = (v[j]-mean)*rstd*g[d] + bb[d];
    }
}

// ---------------- 128x64x16 fp32 GEMM, 8x4 per thread ----------------
// C = act(A @ W^T + bias) [+ res]    (A: MxK, W: NxK, both row-major)
// If gridDim.z > 1: K sliced over z, pure partials written to C + z*M*N.
#define GBM 128
#define GBN 64
#define GBK 16
__global__ __launch_bounds__(256) void gemm_kernel(
    const float* __restrict__ A, const float* __restrict__ W,
    const float* __restrict__ bias, const float* __restrict__ res,
    float* __restrict__ C, int M, int N, int K, int act)
{
    __shared__ float As[GBK][GBM+4];
    __shared__ float Ws[GBK][GBN+4];
    int tid = threadIdx.x;
    int m0 = blockIdx.y*GBM, n0 = blockIdx.x*GBN;
    int S = gridDim.z;
    int Ks = K / S;
    int kbeg = blockIdx.z * Ks;
    int lr = tid >> 2;          // 0..63
    int lc = (tid & 3) * 4;     // 0,4,8,12
    const float* Ap = A + (size_t)(m0 + lr)*K + kbeg + lc;
    const float* Wp = W + (size_t)(n0 + lr)*K + kbeg + lc;
    int ty = tid >> 4, tx = tid & 15;   // 16x16 threads -> (8m x 4n each)

    float acc[8][4] = {};
    // stage first tile in registers
    float4 a0 = *(const float4*)(Ap);
    float4 a1 = *(const float4*)(Ap + (size_t)64*K);
    float4 w0 = *(const float4*)(Wp);

    for (int k0 = 0; k0 < Ks; k0 += GBK) {
        As[lc+0][lr]    = a0.x; As[lc+1][lr]    = a0.y; As[lc+2][lr]    = a0.z; As[lc+3][lr]    = a0.w;
        As[lc+0][lr+64] = a1.x; As[lc+1][lr+64] = a1.y; As[lc+2][lr+64] = a1.z; As[lc+3][lr+64] = a1.w;
        Ws[lc+0][lr]    = w0.x; Ws[lc+1][lr]    = w0.y; Ws[lc+2][lr]    = w0.z; Ws[lc+3][lr]    = w0.w;
        __syncthreads();
        if (k0 + GBK < Ks) {
            a0 = *(const float4*)(Ap + k0 + GBK);
            a1 = *(const float4*)(Ap + k0 + GBK + (size_t)64*K);
            w0 = *(const float4*)(Wp + k0 + GBK);
        }
        #pragma unroll
        for (int k = 0; k < GBK; k++) {
            float ar[8], br[4];
            *(float4*)(ar)   = *(const float4*)&As[k][ty*8];
            *(float4*)(ar+4) = *(const float4*)&As[k][ty*8+4];
            *(float4*)(br)   = *(const float4*)&Ws[k][tx*4];
            #pragma unroll
            for (int i = 0; i < 8; i++)
                #pragma unroll
                for (int j = 0; j < 4; j++)
                    acc[i][j] += ar[i]*br[j];
        }
        __syncthreads();
    }

    if (S > 1) {
        float* Cp = C + (size_t)blockIdx.z*M*N;
        #pragma unroll
        for (int i = 0; i < 8; i++) {
            int m = m0 + ty*8 + i;
            *(float4*)(Cp + (size_t)m*N + n0 + tx*4) = *(float4*)&acc[i][0];
        }
    } else {
        float4 bv = *(const float4*)(bias + n0 + tx*4);
        #pragma unroll
        for (int i = 0; i < 8; i++) {
            int m = m0 + ty*8 + i;
            float vr[4];
            vr[0] = acc[i][0] + bv.x;
            vr[1] = acc[i][1] + bv.y;
            vr[2] = acc[i][2] + bv.z;
            vr[3] = acc[i][3] + bv.w;
            if (act == 1) {
                #pragma unroll
                for (int j = 0; j < 4; j++)
                    vr[j] = 0.5f * vr[j] * (1.0f + erff(vr[j] * 0.7071067811865475f));
            }
            float* dst = C + (size_t)m*N + n0 + tx*4;
            if (res) {
                float4 r0 = *(const float4*)(res + (size_t)m*N + n0 + tx*4);
                vr[0]+=r0.x; vr[1]+=r0.y; vr[2]+=r0.z; vr[3]+=r0.w;
            }
            *(float4*)(dst) = *(float4*)&vr[0];
        }
    }
}

// ---------------- split-K reduce: h += sum_z partial[z] + bias ----------------
__global__ __launch_bounds__(256) void reduce_splitk(const float* __restrict__ P,
                                                     const float* __restrict__ bias,
                                                     float* __restrict__ h,
                                                     int MN, int N) {
    int i4 = blockIdx.x*256 + threadIdx.x;
    if (i4 >= MN/4) return;
    int n = (i4*4) & (N-1);   // N is a power of 2
    const float4* P4 = (const float4*)P;
    int stride4 = MN/4;
    float4 s0 = P4[i4];
    float4 s1 = P4[i4 + stride4];
    float4 s2 = P4[i4 + 2*stride4];
    float4 s3 = P4[i4 + 3*stride4];
    float4 b  = *(const float4*)(bias + n);
    float4 hv = ((float4*)h)[i4];
    hv.x += s0.x + s1.x + s2.x + s3.x + b.x;
    hv.y += s0.y + s1.y + s2.y + s3.y + b.y;
    hv.z += s0.z + s1.z + s2.z + s3.z + b.z;
    hv.w += s0.w + s1.w + s2.w + s3.w + b.w;
    ((float4*)h)[i4] = hv;
}

// ---------------- fused attention (scores + bias + softmax + PV) ----------------
// grid: (Bc*Hc, 8), 256 threads; each warp handles 4 query rows.
__global__ __launch_bounds__(256) void attn_kernel(const float* __restrict__ qkv,
                                                   const float* __restrict__ pr,
                                                   const float* __restrict__ ppw,
                                                   const float* __restrict__ ppb,
                                                   float* __restrict__ out) {
    int b = blockIdx.x >> 6;
    int h = blockIdx.x & 63;
    __shared__ float Ks[Nc*9];   // padded stride 9 -> conflict-free
    __shared__ float Vs[Nc*9];
    int tid = threadIdx.x;
    {
        int n = tid;   // 256 threads, one K/V row each
        const float* kp = qkv + (((b*Nc + n)*3 + 1))*Dc + h*HDc;
        const float* vp = kp + Dc;
        float4 k0 = *(const float4*)kp,     k1 = *(const float4*)(kp+4);
        float4 v0 = *(const float4*)vp,     v1 = *(const float4*)(vp+4);
        float* kd = &Ks[n*9];
        kd[0]=k0.x; kd[1]=k0.y; kd[2]=k0.z; kd[3]=k0.w;
        kd[4]=k1.x; kd[5]=k1.y; kd[6]=k1.z; kd[7]=k1.w;
        float* vd = &Vs[n*9];
        vd[0]=v0.x; vd[1]=v0.y; vd[2]=v0.z; vd[3]=v0.w;
        vd[4]=v1.x; vd[5]=v1.y; vd[6]=v1.z; vd[7]=v1.w;
    }
    __syncthreads();
    const float scale = 0.3535533905932738f;   // 1/sqrt(8)
    float pw = ppw[h], pb = ppb[h];
    int warp = tid >> 5, lane = tid & 31;
    #pragma unroll
    for (int r = 0; r < 4; r++) {
        int i = blockIdx.y*32 + warp*4 + r;
        const float* qp = qkv + ((b*Nc + i)*3)*Dc + h*HDc;
        float4 q0 = *(const float4*)qp, q1 = *(const float4*)(qp+4);
        const float* prow = pr + (b*Nc + i)*Nc;
        float s[8];
        float mx = -1e30f;
        #pragma unroll
        for (int jj = 0; jj < 8; jj++) {
            int j = lane + 32*jj;
            const float* kk = &Ks[j*9];
            float d = q0.x*kk[0] + q0.y*kk[1] + q0.z*kk[2] + q0.w*kk[3]
                    + q1.x*kk[4] + q1.y*kk[5] + q1.z*kk[6] + q1.w*kk[7];
            s[jj] = d*scale + prow[j]*pw + pb;
            mx = fmaxf(mx, s[jj]);
        }
        #pragma unroll
        for (int off = 16; off; off >>= 1)
            mx = fmaxf(mx, __shfl_xor_sync(0xffffffff, mx, off));
        float sum = 0.f;
        #pragma unroll
        for (int jj = 0; jj < 8; jj++) { s[jj] = __expf(s[jj]-mx); sum += s[jj]; }
        #pragma unroll
        for (int off = 16; off; off >>= 1)
            sum += __shfl_xor_sync(0xffffffff, sum, off);
        float inv = 1.0f / sum;
        float acc[8] = {};
        #pragma unroll
        for (int jj = 0; jj < 8; jj++) {
            int j = lane + 32*jj;
            float p = s[jj]*inv;
            const float* vv = &Vs[j*9];
            #pragma unroll
            for (int d = 0; d < 8; d++) acc[d] += p*vv[d];
        }
        #pragma unroll
        for (int off = 16; off; off >>= 1) {
            #pragma unroll
            for (int d = 0; d < 8; d++)
                acc[d] += __shfl_xor_sync(0xffffffff, acc[d], off);
        }
        if (lane == 0) {
            float* op = out + (b*Nc + i)*Dc + h*HDc;
            #pragma unroll
            for (int d = 0; d < 8; d++) op[d] = acc[d];
        }
    }
}

// ---------------- SE(3) coordinate update ----------------
__global__ __launch_bounds__(128) void coords_kernel(const float* __restrict__ coords,
                                                     const float* __restrict__ pr,
                                                     const float* __restrict__ uw,
                                                     const float* __restrict__ ub,
                                                     const float* __restrict__ ww,
                                                     const float* __restrict__ wb,
                                                     float* __restrict__ out) {
    int gw = blockIdx.x * 4 + (threadIdx.x >> 5);  // global warp -> (b,i)
    int lane = threadIdx.x & 31;
    int b = gw >> 8, i = gw & 255;
    float u0 = uw[0], u1 = ub[0], w0 = ww[0], w1 = wb[0];
    const float* ci = coords + (b*Nc + i)*3;
    float cx = ci[0], cy = ci[1], cz = ci[2];
    float ax = 0.f, ay = 0.f, az = 0.f;
    const float* prow = pr + (b*Nc + i)*Nc;
    #pragma unroll
    for (int jj = 0; jj < 8; jj++) {
        int j = lane + 32*jj;
        const float* cj = coords + (b*Nc + j)*3;
        float c = (fmaxf(prow[j], 0.f)*u0 + u1)*w0 + w1;
        ax += (cx - cj[0])*c;
        ay += (cy - cj[1])*c;
        az += (cz - cj[2])*c;
    }
    #pragma unroll
    for (int off = 16; off; off >>= 1) {
        ax += __shfl_xor_sync(0xffffffff, ax, off);
        ay += __shfl_xor_sync(0xffffffff, ay, off);
        az += __shfl_xor_sync(0xffffffff, az, off);
    }
    if (lane == 0) {
        float invn = 1.0f / (256.0f + 1e-6f);
        float* op = out + (b*Nc + i)*3;
        op[0] = cx + ax*invn;
        op[1] = cy + ay*invn;
        op[2] = cz + az*invn;
    }
}

// ---------------- energy head ----------------
__global__ __launch_bounds__(128) void energy_kernel(const float* __restrict__ h,
                                                     const float* __restrict__ enw,
                                                     const float* __restrict__ enb,
                                                     float* __restrict__ out) {
    int b = blockIdx.x;
    int tid = threadIdx.x;
    const float* row = h + (b*Nc)*Dc;   // token 0
    float s = 0.f;
    #pragma unroll
    for (int j = 0; j < 4; j++) {
        int d = tid + 128*j;
        s += row[d]*enw[d];
    }
    #pragma unroll
    for (int off = 16; off; off >>= 1)
        s += __shfl_xor_sync(0xffffffff, s, off);
    __shared__ float rs[4];
    int wid = tid >> 5, lane = tid & 31;
    if (lane == 0) rs[wid] = s;
    __syncthreads();
    if (tid == 0)
        out[Bc*Nc*3 + b] = rs[0]+rs[1]+rs[2]+rs[3] + enb[0];
}

// ---------------- host ----------------
extern "C" void kernel_launch(void* const* d_in, const int* in_sizes, int n_in,
                              void* d_out, int out_size) {
    bool has_mask = (n_in >= 31);
    auto IN = [&](int i) -> const void* {
        int k = i;
        if (!has_mask && i > 3) k = i - 1;
        return d_in[k];
    };
    const int*   atom_types = (const int*)  IN(0);
    const float* coords     = (const float*)IN(1);
    const int*   pair_types = (const int*)  IN(2);
    const float* atom_emb   = (const float*)IN(4);
    const float* gmu        = (const float*)IN(5);
    const float* gsigma     = (const float*)IN(6);
    const float* pair_a     = (const float*)IN(7);
    const float* pair_b     = (const float*)IN(8);
    const float* pl_w       = (const float*)IN(9);
    const float* pl_b       = (const float*)IN(10);
    const float* ln1_g      = (const float*)IN(11);
    const float* ln1_b      = (const float*)IN(12);
    const float* qkv_w      = (const float*)IN(13);
    const float* qkv_b      = (const float*)IN(14);
    const float* pp_w       = (const float*)IN(15);
    const float* pp_b       = (const float*)IN(16);
    const float* out_w      = (const float*)IN(17);
    const float* out_b      = (const float*)IN(18);
    const float* ln2_g      = (const float*)IN(19);
    const float* ln2_b      = (const float*)IN(20);
    const float* ffn_w1     = (const float*)IN(21);
    const float* ffn_b1     = (const float*)IN(22);
    const float* ffn_w2     = (const float*)IN(23);
    const float* ffn_b2     = (const float*)IN(24);
    const float* se3_uw     = (const float*)IN(25);
    const float* se3_ub     = (const float*)IN(26);
    const float* se3_ww     = (const float*)IN(27);
    const float* se3_wb     = (const float*)IN(28);
    const float* en_w       = (const float*)IN(29);
    const float* en_b       = (const float*)IN(30);
    float* out = (float*)d_out;

    float *hb, *xb, *qkvb, *attnb, *ffnb, *pairb, *splitb;
    cudaGetSymbolAddress((void**)&hb,     g_h);
    cudaGetSymbolAddress((void**)&xb,     g_x);
    cudaGetSymbolAddress((void**)&qkvb,   g_qkv);
    cudaGetSymbolAddress((void**)&attnb,  g_attn);
    cudaGetSymbolAddress((void**)&ffnb,   g_ffn);
    cudaGetSymbolAddress((void**)&pairb,  g_pair);
    cudaGetSymbolAddress((void**)&splitb, g_split);

    emb_kernel<<<(Mc*Dc + 255)/256, 256>>>(atom_types, atom_emb, hb);
    pair_kernel<<<(Bc*Nc*Nc)/256, 256>>>(coords, pair_types, pair_a, pair_b,
                                         gmu, gsigma, pl_w, pl_b, pairb);

    for (int l = 0; l < Lc; l++) {
        const float* l1g = ln1_g + l*Dc;
        const float* l1b = ln1_b + l*Dc;
        const float* qw  = qkv_w + (size_t)l*3*Dc*Dc;
        const float* qb  = qkv_b + l*3*Dc;
        const float* pwp = pp_w + l*Hc;
        const float* pbp = pp_b + l*Hc;
        const float* ow  = out_w + (size_t)l*Dc*Dc;
        const float* ob  = out_b + l*Dc;
        const float* l2g = ln2_g + l*Dc;
        const float* l2b = ln2_b + l*Dc;
        const float* w1  = ffn_w1 + (size_t)l*Fc*Dc;
        const float* b1  = ffn_b1 + l*Fc;
        const float* w2  = ffn_w2 + (size_t)l*Dc*Fc;
        const float* b2  = ffn_b2 + l*Dc;

        ln_kernel<<<Mc, 128>>>(hb, l1g, l1b, xb);
        gemm_kernel<<<dim3((3*Dc)/GBN, Mc/GBM, 1), 256>>>(xb, qw, qb, nullptr, qkvb,
                                                          Mc, 3*Dc, Dc, 0);
        attn_kernel<<<dim3(Bc*Hc, 8), 256>>>(qkvb, pairb, pwp, pbp, attnb);
        gemm_kernel<<<dim3(Dc/GBN, Mc/GBM, SPLITK), 256>>>(attnb, ow, nullptr, nullptr,
                                                           splitb, Mc, Dc, Dc, 0);
        reduce_splitk<<<(Mc*Dc/4 + 255)/256, 256>>>(splitb, ob, hb, Mc*Dc, Dc);
        ln_kernel<<<Mc, 128>>>(hb, l2g, l2b, xb);
        gemm_kernel<<<dim3(Fc/GBN, Mc/GBM, 1), 256>>>(xb, w1, b1, nullptr, ffnb,
                                                      Mc, Fc, Dc, 1);
        gemm_kernel<<<dim3(Dc/GBN, Mc/GBM, SPLITK), 256>>>(ffnb, w2, nullptr, nullptr,
                                                           splitb, Mc, Dc, Fc, 0);
        reduce_splitk<<<(Mc*Dc/4 + 255)/256, 256>>>(splitb, b2, hb, Mc*Dc, Dc);
    }

    coords_kernel<<<(Bc*Nc)/4, 128>>>(coords, pairb, se3_uw, se3_ub, se3_ww, se3_wb, out);
    energy_kernel<<<Bc, 128>>>(hb, en_w, en_b, out);
    (void)in_sizes; (void)out_size;
}

// round 4
// speedup vs baseline: 1.5433x; 1.5433x over previous
#include <cuda_runtime.h>
#include <cuda_bf16.h>
#include <mma.h>
#include <math.h>

using namespace nvcuda;

// Problem constants
#define Lc 15
#define Dc 512
#define Hc 64
#define HDc 8
#define Fc 2048
#define Gc 128
#define Bc 4
#define Nc 256
#define Mc (Bc*Nc)   // 1024 rows
#define SPLITK 4

// -------- scratch (device globals; no allocation allowed) --------
__device__ float g_h[Mc*Dc];
__device__ float g_x[Mc*Dc];
__device__ float g_qkv[Mc*3*Dc];
__device__ float g_attn[Mc*Dc];
__device__ float g_ffn[Mc*Fc];
__device__ float g_pair[Bc*Nc*Nc];
__device__ float g_split[SPLITK*Mc*Dc];

// ---------------- embedding ----------------
__global__ void emb_kernel(const int* __restrict__ atom_types,
                           const float* __restrict__ atom_emb,
                           float* __restrict__ h) {
    int idx = blockIdx.x * blockDim.x + threadIdx.x;
    if (idx >= Mc*Dc) return;
    int row = idx >> 9;
    int d   = idx & 511;
    h[idx] = atom_emb[atom_types[row]*Dc + d];
}

// ---------------- pair representation ----------------
__global__ void pair_kernel(const float* __restrict__ coords,
                            const int* __restrict__ ptypes,
                            const float* __restrict__ pa,
                            const float* __restrict__ pb,
                            const float* __restrict__ mu,
                            const float* __restrict__ sigma,
                            const float* __restrict__ plw,
                            const float* __restrict__ plb,
                            float* __restrict__ pr) {
    __shared__ float smu[Gc], scoef[Gc];
    int tid = threadIdx.x;
    if (tid < Gc) {
        float sg = sigma[tid];
        scoef[tid] = plw[tid] / (2.0f*sg*sg) / (sg * 2.5066282746310002f);
        smu[tid]   = mu[tid];
    }
    __syncthreads();
    int p = blockIdx.x * blockDim.x + tid;
    int b = p >> 16;
    int rem = p & 65535;
    int i = rem >> 8, j = rem & 255;
    const float* ci = coords + (b*Nc + i)*3;
    const float* cj = coords + (b*Nc + j)*3;
    float dx = ci[0]-cj[0], dy = ci[1]-cj[1], dz = ci[2]-cj[2];
    float d2 = dx*dx + dy*dy + dz*dz;
    float dist = sqrtf(fmaxf(d2, 1e-12f));
    int pt = ptypes[p];
    float da = pa[pt]*dist + pb[pt];
    float s = 0.f;
    #pragma unroll 8
    for (int g = 0; g < Gc; g++) {
        float t = da - smu[g];
        s += __expf(-t*t) * scoef[g];
    }
    pr[p] = s + plb[0];
}

// ---------------- layernorm ----------------
__global__ __launch_bounds__(128) void ln_kernel(const float* __restrict__ in,
                                                 const float* __restrict__ g,
                                                 const float* __restrict__ bb,
                                                 float* __restrict__ out) {
    int row = blockIdx.x;
    int tid = threadIdx.x;
    const float* x = in + row*Dc;
    float v[4], s = 0.f, s2 = 0.f;
    #pragma unroll
    for (int j = 0; j < 4; j++) {
        v[j] = x[tid + 128*j];
        s += v[j]; s2 += v[j]*v[j];
    }
    #pragma unroll
    for (int off = 16; off; off >>= 1) {
        s  += __shfl_xor_sync(0xffffffff, s,  off);
        s2 += __shfl_xor_sync(0xffffffff, s2, off);
    }
    __shared__ float rs[4], rs2[4];
    int wid = tid >> 5, lane = tid & 31;
    if (lane == 0) { rs[wid] = s; rs2[wid] = s2; }
    __syncthreads();
    s  = rs[0]+rs[1]+rs[2]+rs[3];
    s2 = rs2[0]+rs2[1]+rs2[2]+rs2[3];
    float mean = s * (1.0f/Dc);
    float var  = s2 * (1.0f/Dc) - mean*mean;
    float rstd = rsqrtf(var + 1e-5f);
    #pragma unroll
    for (int j = 0; j < 4; j++) {
        int d = tid + 128*j;
        out[row*Dc + d] = (v[j]-mean)*rstd*g[d] + bb[d];
    }
}

// ---------------- bf16x3 tensor-core GEMM ----------------
// C = act(A @ W^T + bias) [+ res]    (A: MxK fp32, W: NxK fp32)
// fp32 inputs split into bf16 hi+lo; D = Ah*Bh + Ah*Bl + Al*Bh (fp32 acc).
// gridDim.z > 1: K sliced over z, raw partials to C + z*M*N (no epilogue).
#define BM 128
#define BN 64
#define BKT 32
#define LDA 40                 // bf16 ld for A/W tiles (mult of 8)
#define LDC 68                 // fp32 ld for C tile (mult of 4)
__global__ __launch_bounds__(256, 2) void gemm_bf16x3_kernel(
    const float* __restrict__ A, const float* __restrict__ W,
    const float* __restrict__ bias, const float* __restrict__ res,
    float* __restrict__ C, int M, int N, int K, int act)
{
    __shared__ __align__(16) char smem_raw[BM*LDC*4];   // 34816 B (>= 30720 stage)
    __nv_bfloat16* Ah = (__nv_bfloat16*)smem_raw;       // 128*40
    __nv_bfloat16* Al = Ah + BM*LDA;
    __nv_bfloat16* Wh = Al + BM*LDA;                    // 64*40
    __nv_bfloat16* Wl = Wh + BN*LDA;
    float* Ct = (float*)smem_raw;                       // epilogue alias

    int tid = threadIdx.x;
    int m0 = blockIdx.y*BM, n0 = blockIdx.x*BN;
    int S = gridDim.z;
    int Ks = K / S;
    int kbeg = blockIdx.z * Ks;

    int wid = tid >> 5;
    int wm = (wid >> 1) * 32;      // 4 warps along M
    int wn = (wid & 1) * 32;       // 2 warps along N

    wmma::fragment<wmma::accumulator, 16, 16, 16, float> acc[2][2];
    #pragma unroll
    for (int i = 0; i < 2; i++)
        #pragma unroll
        for (int j = 0; j < 2; j++)
            wmma::fill_fragment(acc[i][j], 0.0f);

    // prefetch registers
    float4 pa[4], pw[2];
    #pragma unroll
    for (int i = 0; i < 4; i++) {
        int idx = tid + i*256, row = idx >> 3, c = (idx & 7)*4;
        pa[i] = *(const float4*)(A + (size_t)(m0+row)*K + kbeg + c);
    }
    #pragma unroll
    for (int i = 0; i < 2; i++) {
        int idx = tid + i*256, row = idx >> 3, c = (idx & 7)*4;
        pw[i] = *(const float4*)(W + (size_t)(n0+row)*K + kbeg + c);
    }

    for (int k0 = 0; k0 < Ks; k0 += BKT) {
        // convert + store staged tile
        #pragma unroll
        for (int i = 0; i < 4; i++) {
            int idx = tid + i*256, row = idx >> 3, c = (idx & 7)*4;
            float4 v = pa[i];
            __nv_bfloat16 h0 = __float2bfloat16(v.x), h1 = __float2bfloat16(v.y);
            __nv_bfloat16 h2 = __float2bfloat16(v.z), h3 = __float2bfloat16(v.w);
            __nv_bfloat16 l0 = __float2bfloat16(v.x - __bfloat162float(h0));
            __nv_bfloat16 l1 = __float2bfloat16(v.y - __bfloat162float(h1));
            __nv_bfloat16 l2 = __float2bfloat16(v.z - __bfloat162float(h2));
            __nv_bfloat16 l3 = __float2bfloat16(v.w - __bfloat162float(h3));
            __nv_bfloat162* dh = (__nv_bfloat162*)&Ah[row*LDA + c];
            __nv_bfloat162* dl = (__nv_bfloat162*)&Al[row*LDA + c];
            dh[0] = __halves2bfloat162(h0, h1); dh[1] = __halves2bfloat162(h2, h3);
            dl[0] = __halves2bfloat162(l0, l1); dl[1] = __halves2bfloat162(l2, l3);
        }
        #pragma unroll
        for (int i = 0; i < 2; i++) {
            int idx = tid + i*256, row = idx >> 3, c = (idx & 7)*4;
            float4 v = pw[i];
            __nv_bfloat16 h0 = __float2bfloat16(v.x), h1 = __float2bfloat16(v.y);
            __nv_bfloat16 h2 = __float2bfloat16(v.z), h3 = __float2bfloat16(v.w);
            __nv_bfloat16 l0 = __float2bfloat16(v.x - __bfloat162float(h0));
            __nv_bfloat16 l1 = __float2bfloat16(v.y - __bfloat162float(h1));
            __nv_bfloat16 l2 = __float2bfloat16(v.z - __bfloat162float(h2));
            __nv_bfloat16 l3 = __float2bfloat16(v.w - __bfloat162float(h3));
            __nv_bfloat162* dh = (__nv_bfloat162*)&Wh[row*LDA + c];
            __nv_bfloat162* dl = (__nv_bfloat162*)&Wl[row*LDA + c];
            dh[0] = __halves2bfloat162(h0, h1); dh[1] = __halves2bfloat162(h2, h3);
            dl[0] = __halves2bfloat162(l0, l1); dl[1] = __halves2bfloat162(l2, l3);
        }
        __syncthreads();

        if (k0 + BKT < Ks) {
            #pragma unroll
            for (int i = 0; i < 4; i++) {
                int idx = tid + i*256, row = idx >> 3, c = (idx & 7)*4;
                pa[i] = *(const float4*)(A + (size_t)(m0+row)*K + kbeg + k0 + BKT + c);
            }
            #pragma unroll
            for (int i = 0; i < 2; i++) {
                int idx = tid + i*256, row = idx >> 3, c = (idx & 7)*4;
                pw[i] = *(const float4*)(W + (size_t)(n0+row)*K + kbeg + k0 + BKT + c);
            }
        }

        #pragma unroll
        for (int ks = 0; ks < BKT; ks += 16) {
            wmma::fragment<wmma::matrix_a, 16, 16, 16, __nv_bfloat16, wmma::row_major> ah[2], al[2];
            #pragma unroll
            for (int i = 0; i < 2; i++) {
                wmma::load_matrix_sync(ah[i], Ah + (wm + i*16)*LDA + ks, LDA);
                wmma::load_matrix_sync(al[i], Al + (wm + i*16)*LDA + ks, LDA);
            }
            #pragma unroll
            for (int j = 0; j < 2; j++) {
                wmma::fragment<wmma::matrix_b, 16, 16, 16, __nv_bfloat16, wmma::col_major> bh, bl;
                wmma::load_matrix_sync(bh, Wh + (wn + j*16)*LDA + ks, LDA);
                wmma::load_matrix_sync(bl, Wl + (wn + j*16)*LDA + ks, LDA);
                #pragma unroll
                for (int i = 0; i < 2; i++) {
                    wmma::mma_sync(acc[i][j], ah[i], bh, acc[i][j]);
                    wmma::mma_sync(acc[i][j], ah[i], bl, acc[i][j]);
                    wmma::mma_sync(acc[i][j], al[i], bh, acc[i][j]);
                }
            }
        }
        __syncthreads();
    }

    if (S > 1) {
        // raw partials straight to global
        float* Cp = C + (size_t)blockIdx.z*M*N;
        #pragma unroll
        for (int i = 0; i < 2; i++)
            #pragma unroll
            for (int j = 0; j < 2; j++)
                wmma::store_matrix_sync(Cp + (size_t)(m0+wm+i*16)*N + n0+wn+j*16,
                                        acc[i][j], N, wmma::mem_row_major);
        return;
    }

    // epilogue via smem tile
    #pragma unroll
    for (int i = 0; i < 2; i++)
        #pragma unroll
        for (int j = 0; j < 2; j++)
            wmma::store_matrix_sync(Ct + (wm+i*16)*LDC + wn+j*16,
                                    acc[i][j], LDC, wmma::mem_row_major);
    __syncthreads();

    int col = (tid & 15) * 4;
    int r0  = tid >> 4;            // 0..15
    float4 bv = make_float4(0.f, 0.f, 0.f, 0.f);
    if (bias) bv = *(const float4*)(bias + n0 + col);
    #pragma unroll
    for (int rr = 0; rr < 8; rr++) {
        int row = rr*16 + r0;
        float vr[4];
        *(float4*)vr = *(const float4*)&Ct[row*LDC + col];
        vr[0] += bv.x; vr[1] += bv.y; vr[2] += bv.z; vr[3] += bv.w;
        if (act == 1) {
            #pragma unroll
            for (int j = 0; j < 4; j++)
                vr[j] = 0.5f * vr[j] * (1.0f + erff(vr[j] * 0.7071067811865475f));
        }
        float* dst = C + (size_t)(m0+row)*N + n0 + col;
        if (res) {
            float4 r = *(const float4*)(res + (size_t)(m0+row)*N + n0 + col);
            vr[0]+=r.x; vr[1]+=r.y; vr[2]+=r.z; vr[3]+=r.w;
        }
        *(float4*)dst = *(float4*)vr;
    }
}

// ---------------- split-K reduce: h += sum_z partial[z] + bias ----------------
__global__ __launch_bounds__(256) void reduce_splitk(const float* __restrict__ P,
                                                     const float* __restrict__ bias,
                                                     float* __restrict__ h,
                                                     int MN, int N) {
    int i4 = blockIdx.x*256 + threadIdx.x;
    if (i4 >= MN/4) return;
    int n = (i4*4) & (N-1);
    const float4* P4 = (const float4*)P;
    int stride4 = MN/4;
    float4 s0 = P4[i4];
    float4 s1 = P4[i4 + stride4];
    float4 s2 = P4[i4 + 2*stride4];
    float4 s3 = P4[i4 + 3*stride4];
    float4 b  = *(const float4*)(bias + n);
    float4 hv = ((float4*)h)[i4];
    hv.x += s0.x + s1.x + s2.x + s3.x + b.x;
    hv.y += s0.y + s1.y + s2.y + s3.y + b.y;
    hv.z += s0.z + s1.z + s2.z + s3.z + b.z;
    hv.w += s0.w + s1.w + s2.w + s3.w + b.w;
    ((float4*)h)[i4] = hv;
}

// ---------------- fused attention (QKV bias + scores + softmax + PV) ----------------
// grid: (Bc*Hc, 8), 256 threads; each warp handles 4 query rows.
// qkv holds the RAW (bias-free) GEMM output; biases applied here.
__global__ __launch_bounds__(256) void attn_kernel(const float* __restrict__ qkv,
                                                   const float* __restrict__ qb,
                                                   const float* __restrict__ pr,
                                                   const float* __restrict__ ppw,
                                                   const float* __restrict__ ppb,
                                                   float* __restrict__ out) {
    int b = blockIdx.x >> 6;
    int h = blockIdx.x & 63;
    __shared__ float Ks[Nc*9];
    __shared__ float Vs[Nc*9];
    int tid = threadIdx.x;
    // per-head biases
    float4 bq0 = *(const float4*)(qb + h*HDc);
    float4 bq1 = *(const float4*)(qb + h*HDc + 4);
    float4 bk0 = *(const float4*)(qb + Dc + h*HDc);
    float4 bk1 = *(const float4*)(qb + Dc + h*HDc + 4);
    float4 bv0 = *(const float4*)(qb + 2*Dc + h*HDc);
    float4 bv1 = *(const float4*)(qb + 2*Dc + h*HDc + 4);
    {
        int n = tid;
        const float* kp = qkv + (((b*Nc + n)*3 + 1))*Dc + h*HDc;
        const float* vp = kp + Dc;
        float4 k0 = *(const float4*)kp,     k1 = *(const float4*)(kp+4);
        float4 v0 = *(const float4*)vp,     v1 = *(const float4*)(vp+4);
        float* kd = &Ks[n*9];
        kd[0]=k0.x+bk0.x; kd[1]=k0.y+bk0.y; kd[2]=k0.z+bk0.z; kd[3]=k0.w+bk0.w;
        kd[4]=k1.x+bk1.x; kd[5]=k1.y+bk1.y; kd[6]=k1.z+bk1.z; kd[7]=k1.w+bk1.w;
        float* vd = &Vs[n*9];
        vd[0]=v0.x+bv0.x; vd[1]=v0.y+bv0.y; vd[2]=v0.z+bv0.z; vd[3]=v0.w+bv0.w;
        vd[4]=v1.x+bv1.x; vd[5]=v1.y+bv1.y; vd[6]=v1.z+bv1.z; vd[7]=v1.w+bv1.w;
    }
    __syncthreads();
    const float scale = 0.3535533905932738f;
    float pw = ppw[h], pb = ppb[h];
    int warp = tid >> 5, lane = tid & 31;
    #pragma unroll
    for (int r = 0; r < 4; r++) {
        int i = blockIdx.y*32 + warp*4 + r;
        const float* qp = qkv + ((b*Nc + i)*3)*Dc + h*HDc;
        float4 q0 = *(const float4*)qp, q1 = *(const float4*)(qp+4);
        float qr[8];
        qr[0]=q0.x+bq0.x; qr[1]=q0.y+bq0.y; qr[2]=q0.z+bq0.z; qr[3]=q0.w+bq0.w;
        qr[4]=q1.x+bq1.x; qr[5]=q1.y+bq1.y; qr[6]=q1.z+bq1.z; qr[7]=q1.w+bq1.w;
        const float* prow = pr + (b*Nc + i)*Nc;
        float s[8];
        float mx = -1e30f;
        #pragma unroll
        for (int jj = 0; jj < 8; jj++) {
            int j = lane + 32*jj;
            const float* kk = &Ks[j*9];
            float d = qr[0]*kk[0] + qr[1]*kk[1] + qr[2]*kk[2] + qr[3]*kk[3]
                    + qr[4]*kk[4] + qr[5]*kk[5] + qr[6]*kk[6] + qr[7]*kk[7];
            s[jj] = d*scale + prow[j]*pw + pb;
            mx = fmaxf(mx, s[jj]);
        }
        #pragma unroll
        for (int off = 16; off; off >>= 1)
            mx = fmaxf(mx, __shfl_xor_sync(0xffffffff, mx, off));
        float sum = 0.f;
        #pragma unroll
        for (int jj = 0; jj < 8; jj++) { s[jj] = __expf(s[jj]-mx); sum += s[jj]; }
        #pragma unroll
        for (int off = 16; off; off >>= 1)
            sum += __shfl_xor_sync(0xffffffff, sum, off);
        float inv = 1.0f / sum;
        float acc[8] = {};
        #pragma unroll
        for (int jj = 0; jj < 8; jj++) {
            int j = lane + 32*jj;
            float p = s[jj]*inv;
            const float* vv = &Vs[j*9];
            #pragma unroll
            for (int d = 0; d < 8; d++) acc[d] += p*vv[d];
        }
        #pragma unroll
        for (int off = 16; off; off >>= 1) {
            #pragma unroll
            for (int d = 0; d < 8; d++)
                acc[d] += __shfl_xor_sync(0xffffffff, acc[d], off);
        }
        if (lane == 0) {
            float* op = out + (b*Nc + i)*Dc + h*HDc;
            #pragma unroll
            for (int d = 0; d < 8; d++) op[d] = acc[d];
        }
    }
}

// ---------------- SE(3) coordinate update ----------------
__global__ __launch_bounds__(128) void coords_kernel(const float* __restrict__ coords,
                                                     const float* __restrict__ pr,
                                                     const float* __restrict__ uw,
                                                     const float* __restrict__ ub,
                                                     const float* __restrict__ ww,
                                                     const float* __restrict__ wb,
                                                     float* __restrict__ out) {
    int gw = blockIdx.x * 4 + (threadIdx.x >> 5);
    int lane = threadIdx.x & 31;
    int b = gw >> 8, i = gw & 255;
    float u0 = uw[0], u1 = ub[0], w0 = ww[0], w1 = wb[0];
    const float* ci = coords + (b*Nc + i)*3;
    float cx = ci[0], cy = ci[1], cz = ci[2];
    float ax = 0.f, ay = 0.f, az = 0.f;
    const float* prow = pr + (b*Nc + i)*Nc;
    #pragma unroll
    for (int jj = 0; jj < 8; jj++) {
        int j = lane + 32*jj;
        const float* cj = coords + (b*Nc + j)*3;
        float c = (fmaxf(prow[j], 0.f)*u0 + u1)*w0 + w1;
        ax += (cx - cj[0])*c;
        ay += (cy - cj[1])*c;
        az += (cz - cj[2])*c;
    }
    #pragma unroll
    for (int off = 16; off; off >>= 1) {
        ax += __shfl_xor_sync(0xffffffff, ax, off);
        ay += __shfl_xor_sync(0xffffffff, ay, off);
        az += __shfl_xor_sync(0xffffffff, az, off);
    }
    if (lane == 0) {
        float invn = 1.0f / (256.0f + 1e-6f);
        float* op = out + (b*Nc + i)*3;
        op[0] = cx + ax*invn;
        op[1] = cy + ay*invn;
        op[2] = cz + az*invn;
    }
}

// ---------------- energy head ----------------
__global__ __launch_bounds__(128) void energy_kernel(const float* __restrict__ h,
                                                     const float* __restrict__ enw,
                                                     const float* __restrict__ enb,
                                                     float* __restrict__ out) {
    int b = blockIdx.x;
    int tid = threadIdx.x;
    const float* row = h + (b*Nc)*Dc;
    float s = 0.f;
    #pragma unroll
    for (int j = 0; j < 4; j++) {
        int d = tid + 128*j;
        s += row[d]*enw[d];
    }
    #pragma unroll
    for (int off = 16; off; off >>= 1)
        s += __shfl_xor_sync(0xffffffff, s, off);
    __shared__ float rs[4];
    int wid = tid >> 5, lane = tid & 31;
    if (lane == 0) rs[wid] = s;
    __syncthreads();
    if (tid == 0)
        out[Bc*Nc*3 + b] = rs[0]+rs[1]+rs[2]+rs[3] + enb[0];
}

// ---------------- host ----------------
extern "C" void kernel_launch(void* const* d_in, const int* in_sizes, int n_in,
                              void* d_out, int out_size) {
    bool has_mask = (n_in >= 31);
    auto IN = [&](int i) -> const void* {
        int k = i;
        if (!has_mask && i > 3) k = i - 1;
        return d_in[k];
    };
    const int*   atom_types = (const int*)  IN(0);
    const float* coords     = (const float*)IN(1);
    const int*   pair_types = (const int*)  IN(2);
    const float* atom_emb   = (const float*)IN(4);
    const float* gmu        = (const float*)IN(5);
    const float* gsigma     = (const float*)IN(6);
    const float* pair_a     = (const float*)IN(7);
    const float* pair_b     = (const float*)IN(8);
    const float* pl_w       = (const float*)IN(9);
    const float* pl_b       = (const float*)IN(10);
    const float* ln1_g      = (const float*)IN(11);
    const float* ln1_b      = (const float*)IN(12);
    const float* qkv_w      = (const float*)IN(13);
    const float* qkv_b      = (const float*)IN(14);
    const float* pp_w       = (const float*)IN(15);
    const float* pp_b       = (const float*)IN(16);
    const float* out_w      = (const float*)IN(17);
    const float* out_b      = (const float*)IN(18);
    const float* ln2_g      = (const float*)IN(19);
    const float* ln2_b      = (const float*)IN(20);
    const float* ffn_w1     = (const float*)IN(21);
    const float* ffn_b1     = (const float*)IN(22);
    const float* ffn_w2     = (const float*)IN(23);
    const float* ffn_b2     = (const float*)IN(24);
    const float* se3_uw     = (const float*)IN(25);
    const float* se3_ub     = (const float*)IN(26);
    const float* se3_ww     = (const float*)IN(27);
    const float* se3_wb     = (const float*)IN(28);
    const float* en_w       = (const float*)IN(29);
    const float* en_b       = (const float*)IN(30);
    float* out = (float*)d_out;

    float *hb, *xb, *qkvb, *attnb, *ffnb, *pairb, *splitb;
    cudaGetSymbolAddress((void**)&hb,     g_h);
    cudaGetSymbolAddress((void**)&xb,     g_x);
    cudaGetSymbolAddress((void**)&qkvb,   g_qkv);
    cudaGetSymbolAddress((void**)&attnb,  g_attn);
    cudaGetSymbolAddress((void**)&ffnb,   g_ffn);
    cudaGetSymbolAddress((void**)&pairb,  g_pair);
    cudaGetSymbolAddress((void**)&splitb, g_split);

    emb_kernel<<<(Mc*Dc + 255)/256, 256>>>(atom_types, atom_emb, hb);
    pair_kernel<<<(Bc*Nc*Nc)/256, 256>>>(coords, pair_types, pair_a, pair_b,
                                         gmu, gsigma, pl_w, pl_b, pairb);

    for (int l = 0; l < Lc; l++) {
        const float* l1g = ln1_g + l*Dc;
        const float* l1b = ln1_b + l*Dc;
        const float* qw  = qkv_w + (size_t)l*3*Dc*Dc;
        const float* qb  = qkv_b + l*3*Dc;
        const float* pwp = pp_w + l*Hc;
        const float* pbp = pp_b + l*Hc;
        const float* ow  = out_w + (size_t)l*Dc*Dc;
        const float* ob  = out_b + l*Dc;
        const float* l2g = ln2_g + l*Dc;
        const float* l2b = ln2_b + l*Dc;
        const float* w1  = ffn_w1 + (size_t)l*Fc*Dc;
        const float* b1  = ffn_b1 + l*Fc;
        const float* w2  = ffn_w2 + (size_t)l*Dc*Fc;
        const float* b2  = ffn_b2 + l*Dc;

        ln_kernel<<<Mc, 128>>>(hb, l1g, l1b, xb);
        // QKV: raw output (bias folded into attention)
        gemm_bf16x3_kernel<<<dim3((3*Dc)/BN, Mc/BM, 1), 256>>>(xb, qw, nullptr, nullptr,
                                                               qkvb, Mc, 3*Dc, Dc, 0);
        attn_kernel<<<dim3(Bc*Hc, 8), 256>>>(qkvb, qb, pairb, pwp, pbp, attnb);
        gemm_bf16x3_kernel<<<dim3(Dc/BN, Mc/BM, SPLITK), 256>>>(attnb, ow, nullptr, nullptr,
                                                                splitb, Mc, Dc, Dc, 0);
        reduce_splitk<<<(Mc*Dc/4 + 255)/256, 256>>>(splitb, ob, hb, Mc*Dc, Dc);
        ln_kernel<<<Mc, 128>>>(hb, l2g, l2b, xb);
        gemm_bf16x3_kernel<<<dim3(Fc/BN, Mc/BM, 1), 256>>>(xb, w1, b1, nullptr,
                                                           ffnb, Mc, Fc, Dc, 1);
        gemm_bf16x3_kernel<<<dim3(Dc/BN, Mc/BM, SPLITK), 256>>>(ffnb, w2, nullptr, nullptr,
                                                                splitb, Mc, Dc, Fc, 0);
        reduce_splitk<<<(Mc*Dc/4 + 255)/256, 256>>>(splitb, b2, hb, Mc*Dc, Dc);
    }

    coords_kernel<<<(Bc*Nc)/4, 128>>>(coords, pairb, se3_uw, se3_ub, se3_ww, se3_wb, out);
    energy_kernel<<<Bc, 128>>>(hb, en_w, en_b, out);
    (void)in_sizes; (void)out_size;
}